// round 7
// baseline (speedup 1.0000x reference)
#include <cuda_runtime.h>
#include <stdint.h>

// x:   [B=32, T=256, HW=3136] fp32 (exact 0.0/1.0 values)
// idx: [C=64, k=4] int32 in [0,256)
// out: [B, C=64, HW] fp32 = (x[e0]+x[e1]+x[e2]+x[e3] >= 2) ? 1 : 0
#define B_    32
#define T_    256
#define HW_   3136
#define C_    64
#define NGRP  49               // 3136 = 49 * 64 : EXACT position groups of 64

// Fused gather kernel, position-split tiling:
// block (256 thr) owns (b, g): 64 positions x all 64 output channels.
// Grid = 32*49 = 1568 blocks, zero tail waste (3136 divides evenly by 64).
// Position-split (unlike R5's channel-split) does NOT duplicate gather-row
// fetches: each 256B half-row is read by exactly one block, so DRAM unique
// traffic stays 65 MB reads + 25.7 MB writes. Within a block, the 256
// channel-gathers hit only ~162 unique 256B rows (~41 KB) -> repeats are
// L1 hits. Streaming stores keep L2 for the gather path.
__global__ void __launch_bounds__(256)
rp_fused(const float* __restrict__ x, const int* __restrict__ idx,
         float* __restrict__ out) {
    __shared__ int s_idx[C_ * 4];

    const int tid  = threadIdx.x;
    const int warp = tid >> 5;
    const int lane = tid & 31;

    s_idx[tid] = __ldg(idx + tid);          // 256 routing entries
    __syncthreads();

    const int blk = blockIdx.x;             // 1568 = 32 * 49
    const int b   = blk / NGRP;
    const int g   = blk - b * NGRP;
    const int pos = g * 64 + lane * 2;      // always in-bounds: 49*64 = 3136

    const float* xb = x   + ((size_t)b * T_) * HW_ + pos;
    float*       ob = out + ((size_t)b * C_) * HW_ + pos;

    // Warp computes 8 contiguous channels; 2 channels per inner step ->
    // 8 independent LDG.64 in flight per thread.
    #pragma unroll
    for (int j0 = 0; j0 < 8; j0 += 2) {
        float2 v[2][4];
        #pragma unroll
        for (int u = 0; u < 2; u++) {
            const int c  = warp * 8 + j0 + u;
            const int e0 = s_idx[c * 4 + 0];
            const int e1 = s_idx[c * 4 + 1];
            const int e2 = s_idx[c * 4 + 2];
            const int e3 = s_idx[c * 4 + 3];
            v[u][0] = *(const float2*)(xb + (size_t)e0 * HW_);
            v[u][1] = *(const float2*)(xb + (size_t)e1 * HW_);
            v[u][2] = *(const float2*)(xb + (size_t)e2 * HW_);
            v[u][3] = *(const float2*)(xb + (size_t)e3 * HW_);
        }
        #pragma unroll
        for (int u = 0; u < 2; u++) {
            const int c = warp * 8 + j0 + u;
            float2 r;
            r.x = ((v[u][0].x + v[u][1].x) + (v[u][2].x + v[u][3].x) >= 2.0f) ? 1.0f : 0.0f;
            r.y = ((v[u][0].y + v[u][1].y) + (v[u][2].y + v[u][3].y) >= 2.0f) ? 1.0f : 0.0f;
            __stcs((float2*)(ob + (size_t)c * HW_), r);
        }
    }
}

extern "C" void kernel_launch(void* const* d_in, const int* in_sizes, int n_in,
                              void* d_out, int out_size) {
    const float* x   = (const float*)d_in[0];
    const int*   idx = (const int*)  d_in[1];
    float*       out = (float*)d_out;
    (void)in_sizes; (void)n_in; (void)out_size;

    rp_fused<<<B_ * NGRP, 256>>>(x, idx, out);   // 1568 blocks
}

// round 8
// speedup vs baseline: 1.0284x; 1.0284x over previous
#include <cuda_runtime.h>
#include <stdint.h>

// x:   [B=32, T=256, HW=3136] fp32 (exact 0.0/1.0 values)
// idx: [C=64, k=4] int32 in [0,256)
// out: [B, C=64, HW] fp32 = (x[e0]+x[e1]+x[e2]+x[e3] >= 2) ? 1 : 0
//
// Note: the reference's STE expression stop_grad(y_hard - y_soft) + y_soft is
// numerically exactly y_hard, so the kernel computes the hard threshold only
// (rel_err has measured 0.0 across all rounds).
#define B_    32
#define T_    256
#define HW_   3136
#define C_    64
#define NGRP  25               // ceil(3136/128) position groups of 128 floats

// Champion structure (R6, 12.4us — at the ~91 MB HBM traffic floor):
// block (256 thr) owns (b, g): 128 positions x all 64 output channels.
// - Each (b,g) slice is touched by exactly ONE block, so the 256 channel-
//   gathers hit only ~162 unique 512B rows (~83 KB) -> repeats are L1/L2
//   hits; DRAM sees only unique reads (65 MB of used channels) + writes
//   (25.7 MB). Unused input channels are never read.
// - Grid 800 CTAs = single wave on 148 SMs (6 blocks/SM at 40 regs).
// - 2 channels per inner step -> 8 independent LDG.128 in flight per thread
//   (~2 KB/thread; MLP oversupplied vs latency*BW requirement).
// - __stcs streaming stores: output is never re-read; keep L2 for the
//   gather-reuse path.
__global__ void __launch_bounds__(256)
rp_fused(const float* __restrict__ x, const int* __restrict__ idx,
         float* __restrict__ out) {
    __shared__ int s_idx[C_ * 4];

    const int tid  = threadIdx.x;
    const int warp = tid >> 5;
    const int lane = tid & 31;

    s_idx[tid] = __ldg(idx + tid);          // 256 routing entries
    __syncthreads();

    const int blk = blockIdx.x;             // 800 = 32 * 25
    const int b   = blk / NGRP;
    const int g   = blk - b * NGRP;
    const int pos = g * 128 + lane * 4;
    const bool ok = (pos < HW_);            // tail group g=24: 64 valid pos

    const float* xb = x   + ((size_t)b * T_) * HW_ + pos;
    float*       ob = out + ((size_t)b * C_) * HW_ + pos;

    #pragma unroll
    for (int j0 = 0; j0 < 8; j0 += 2) {
        float4 v[2][4];
        #pragma unroll
        for (int u = 0; u < 2; u++) {
            const int c  = warp * 8 + j0 + u;
            const int e0 = s_idx[c * 4 + 0];
            const int e1 = s_idx[c * 4 + 1];
            const int e2 = s_idx[c * 4 + 2];
            const int e3 = s_idx[c * 4 + 3];
            if (ok) {
                v[u][0] = *(const float4*)(xb + (size_t)e0 * HW_);
                v[u][1] = *(const float4*)(xb + (size_t)e1 * HW_);
                v[u][2] = *(const float4*)(xb + (size_t)e2 * HW_);
                v[u][3] = *(const float4*)(xb + (size_t)e3 * HW_);
            }
        }
        #pragma unroll
        for (int u = 0; u < 2; u++) {
            const int c = warp * 8 + j0 + u;
            if (ok) {
                float4 r;
                r.x = ((v[u][0].x + v[u][1].x) + (v[u][2].x + v[u][3].x) >= 2.0f) ? 1.0f : 0.0f;
                r.y = ((v[u][0].y + v[u][1].y) + (v[u][2].y + v[u][3].y) >= 2.0f) ? 1.0f : 0.0f;
                r.z = ((v[u][0].z + v[u][1].z) + (v[u][2].z + v[u][3].z) >= 2.0f) ? 1.0f : 0.0f;
                r.w = ((v[u][0].w + v[u][1].w) + (v[u][2].w + v[u][3].w) >= 2.0f) ? 1.0f : 0.0f;
                __stcs((float4*)(ob + (size_t)c * HW_), r);
            }
        }
    }
}

extern "C" void kernel_launch(void* const* d_in, const int* in_sizes, int n_in,
                              void* d_out, int out_size) {
    const float* x   = (const float*)d_in[0];
    const int*   idx = (const int*)  d_in[1];
    float*       out = (float*)d_out;
    (void)in_sizes; (void)n_in; (void)out_size;

    rp_fused<<<B_ * NGRP, 256>>>(x, idx, out);   // 800 blocks, single wave
}

// round 9
// speedup vs baseline: 1.0364x; 1.0078x over previous
#include <cuda_runtime.h>
#include <stdint.h>

// x:   [B=32, T=256, HW=3136] fp32 (exact 0.0/1.0 values)
// idx: [C=64, k=4] int32 in [0,256)
// out: [B, C=64, HW] fp32 = (x[e0]+x[e1]+x[e2]+x[e3] >= 2) ? 1 : 0
//
// The reference's STE expression stop_grad(y_hard - y_soft) + y_soft is
// numerically exactly y_hard, so the kernel computes the hard threshold only
// (rel_err measured 0.0 on every round).
#define B_    32
#define T_    256
#define HW_   3136
#define C_    64
#define NGRP  25               // ceil(3136/128) position groups of 128 floats

// FINAL champion (12.42us, reproduced twice; ~91 MB mandatory HBM traffic
// at ~7.3 TB/s effective -> at the memory floor):
// block (256 thr) owns (b, g): 128 positions x all 64 output channels.
// - Each (b,g) slice is touched by exactly ONE block, so the 256 channel-
//   gathers hit only ~162 unique 512B rows (~83 KB) -> repeats are L1/L2
//   hits; DRAM sees only unique reads (65 MB of used channels) + writes
//   (25.7 MB). Unused input channels are never read.
// - Grid 800 CTAs = single wave on 148 SMs (6 blocks/SM at 40 regs).
// - 2 channels per inner step -> 8 independent LDG.128 in flight per thread
//   (~2 KB/thread; MLP oversupplied vs the latency*BW requirement).
// - __stcs streaming stores: output is never re-read; keep L2 for the
//   gather-reuse path.
// Falsified alternatives: channel-split grid (R5, duplicated gather reads),
// 64-float position groups / LDG.64 (R7, 2x L1 wavefronts per byte),
// separate pack/majority pipeline through a bit-plane scratch (R2/R3).
__global__ void __launch_bounds__(256)
rp_fused(const float* __restrict__ x, const int* __restrict__ idx,
         float* __restrict__ out) {
    __shared__ int s_idx[C_ * 4];

    const int tid  = threadIdx.x;
    const int warp = tid >> 5;
    const int lane = tid & 31;

    s_idx[tid] = __ldg(idx + tid);          // 256 routing entries
    __syncthreads();

    const int blk = blockIdx.x;             // 800 = 32 * 25
    const int b   = blk / NGRP;
    const int g   = blk - b * NGRP;
    const int pos = g * 128 + lane * 4;
    const bool ok = (pos < HW_);            // tail group g=24: 64 valid pos

    const float* xb = x   + ((size_t)b * T_) * HW_ + pos;
    float*       ob = out + ((size_t)b * C_) * HW_ + pos;

    #pragma unroll
    for (int j0 = 0; j0 < 8; j0 += 2) {
        float4 v[2][4];
        #pragma unroll
        for (int u = 0; u < 2; u++) {
            const int c  = warp * 8 + j0 + u;
            const int e0 = s_idx[c * 4 + 0];
            const int e1 = s_idx[c * 4 + 1];
            const int e2 = s_idx[c * 4 + 2];
            const int e3 = s_idx[c * 4 + 3];
            if (ok) {
                v[u][0] = *(const float4*)(xb + (size_t)e0 * HW_);
                v[u][1] = *(const float4*)(xb + (size_t)e1 * HW_);
                v[u][2] = *(const float4*)(xb + (size_t)e2 * HW_);
                v[u][3] = *(const float4*)(xb + (size_t)e3 * HW_);
            }
        }
        #pragma unroll
        for (int u = 0; u < 2; u++) {
            const int c = warp * 8 + j0 + u;
            if (ok) {
                float4 r;
                r.x = ((v[u][0].x + v[u][1].x) + (v[u][2].x + v[u][3].x) >= 2.0f) ? 1.0f : 0.0f;
                r.y = ((v[u][0].y + v[u][1].y) + (v[u][2].y + v[u][3].y) >= 2.0f) ? 1.0f : 0.0f;
                r.z = ((v[u][0].z + v[u][1].z) + (v[u][2].z + v[u][3].z) >= 2.0f) ? 1.0f : 0.0f;
                r.w = ((v[u][0].w + v[u][1].w) + (v[u][2].w + v[u][3].w) >= 2.0f) ? 1.0f : 0.0f;
                __stcs((float4*)(ob + (size_t)c * HW_), r);
            }
        }
    }
}

extern "C" void kernel_launch(void* const* d_in, const int* in_sizes, int n_in,
                              void* d_out, int out_size) {
    const float* x   = (const float*)d_in[0];
    const int*   idx = (const int*)  d_in[1];
    float*       out = (float*)d_out;
    (void)in_sizes; (void)n_in; (void)out_size;

    rp_fused<<<B_ * NGRP, 256>>>(x, idx, out);   // 800 blocks, single wave
}